// round 15
// baseline (speedup 1.0000x reference)
#include <cuda_runtime.h>
#include <cuda_fp16.h>
#include <cstdint>
#include <cstddef>

// R15: R8 (best, 3030us) + 16 producer CTAs on the otherwise-idle SMs.
// All legacy math paths measured at ~32-35 MACs/cyc/SMSP (shared SIMD pipe);
// R8 saturates it on 128 CTAs. Only lever left: use more SMs. Helpers
// (CTAs 128..143, one per 64-col j-slice) precompute xz = x@Wx for steps
// s%4==3 into g_xz (fp16), flagged by monotonic per-slice counters. Mains
// skip the x k-steps on those steps (192 -> 128 MMA/SMSP) and add xz.

#define SEQ   512
#define BATCH 512
#define DIM   128
#define HID   256
#define G4    1024
#define NMAIN 128
#define NHELP 16
#define NCTA  (NMAIN + NHELP)
#define NTHR  256
#define NKS   24
#define NGRP  16

// ---- persistent device scratch ----
__device__ __align__(16) __half g_h16[2][BATCH * HID];
__device__ __align__(16) __half g_xz[(size_t)128 * BATCH * G4];   // 134MB
__device__ unsigned long long g_xzflag[NHELP];
__device__ __align__(128) unsigned long long g_bar_grp[8][16];
__device__ unsigned long long g_bar_all = 0;

__device__ __forceinline__ uint32_t smem_u32(const void* p) {
    uint32_t a;
    asm("{ .reg .u64 t; cvta.to.shared.u64 t, %1; cvt.u32.u64 %0, t; }"
        : "=r"(a) : "l"(p));
    return a;
}
__device__ __forceinline__ void ldsm4(uint32_t a[4], uint32_t addr) {
    asm volatile("ldmatrix.sync.aligned.m8n8.x4.shared.b16 {%0,%1,%2,%3}, [%4];"
                 : "=r"(a[0]), "=r"(a[1]), "=r"(a[2]), "=r"(a[3]) : "r"(addr));
}
__device__ __forceinline__ void mma_f16acc(uint32_t c[2], const uint32_t a[4],
                                           uint32_t b0, uint32_t b1) {
    asm volatile(
        "mma.sync.aligned.m16n8k16.row.col.f16.f16.f16.f16 "
        "{%0,%1}, {%2,%3,%4,%5}, {%6,%7}, {%0,%1};"
        : "+r"(c[0]), "+r"(c[1])
        : "r"(a[0]), "r"(a[1]), "r"(a[2]), "r"(a[3]), "r"(b0), "r"(b1));
}
__device__ __forceinline__ void promote(float acc[4], uint32_t hc[2]) {
    float2 lo = __half22float2(*reinterpret_cast<__half2*>(&hc[0]));
    float2 hi = __half22float2(*reinterpret_cast<__half2*>(&hc[1]));
    acc[0] += lo.x; acc[1] += lo.y; acc[2] += hi.x; acc[3] += hi.y;
    hc[0] = 0u; hc[1] = 0u;
}
__device__ __forceinline__ float tanh_mufu(float x) {
    float y;
    asm("tanh.approx.f32 %0, %1;" : "=f"(y) : "f"(x));
    return y;
}
__device__ __forceinline__ float sig_mufu(float x) {
    return fmaf(0.5f, tanh_mufu(0.5f * x), 0.5f);
}
__device__ __forceinline__ uint32_t a_phys(int ks, int row, int kh) {
    return (uint32_t)(ks * 2048 + row * 32 + ((kh << 4) ^ ((row & 4) << 2)));
}

// monotonic ticket barrier over n participants on counter *ctr (replay-safe)
__device__ __forceinline__ void ticket_barrier(unsigned long long* ctr, int n) {
    __syncthreads();
    if (threadIdx.x == 0) {
        __threadfence();
        unsigned long long t = atomicAdd(ctr, 1ULL) + 1ULL;
        unsigned long long target =
            ((t + (unsigned long long)n - 1ULL) / n) * (unsigned long long)n;
        unsigned long long v;
        do {
            asm volatile("ld.acquire.gpu.u64 %0, [%1];" : "=l"(v) : "l"(ctr) : "memory");
        } while (v < target);
    }
    __syncthreads();
}

__global__ void __launch_bounds__(NTHR, 1)
lstm_prod(const float* __restrict__ x,  const float* __restrict__ Wx,
          const float* __restrict__ Wh, const float* __restrict__ bv,
          const float* __restrict__ Wd, const float* __restrict__ bd,
          float* __restrict__ out)
{
    __shared__ __align__(1024) char sA[NKS * 2048];   // 48 KB
    const uint32_t sA_u = smem_u32(sA);

    const int tid  = threadIdx.x;
    const int cta  = blockIdx.x;
    const int warp = tid >> 5, lane = tid & 31;
    const int wM = warp & 1;            // 2-way M split (32 rows)
    const int wN = warp >> 1;           // 4-way N split (16 n-cols)
    const int q = lane & 3;

    // fragment coordinate maps (shared by helper-write and main-read)
    int Rr[4], cloc[4];
    #pragma unroll
    for (int rj = 0; rj < 4; ++rj) Rr[rj] = wM * 32 + (lane >> 2) + rj * 8;
    cloc[0] = wN * 16 + 2 * q;     cloc[1] = cloc[0] + 1;
    cloc[2] = wN * 16 + 8 + 2 * q; cloc[3] = cloc[2] + 1;

    // loader coords (R8)
    const int xrow = tid >> 2, xkb = (tid & 3) * 32;
    const int hkb  = (tid & 3) * 64;
    const int lrow = lane & 15, lkh = lane >> 4;
    uint32_t lds0 = sA_u + a_phys(0, wM * 32 + lrow, lkh);
    uint32_t lds1 = sA_u + a_phys(0, wM * 32 + 16 + lrow, lkh);

    // =====================================================================
    //  HELPER CTAs: produce xz for steps s = 4t+3 into g_xz[t]
    // =====================================================================
    if (cta >= NMAIN) {
        const int kh = cta - NMAIN;            // j-slice 0..15
        const int j0h = kh * 16;

        // Wx fragments for 8 k-steps of this slice
        uint32_t bx[8][2][2];
        #pragma unroll
        for (int bi = 0; bi < 8; ++bi)
            #pragma unroll
            for (int nb = 0; nb < 2; ++nb) {
                int n = wN * 16 + nb * 8 + (lane >> 2);
                int col = (n & 3) * HID + j0h + (n >> 2);
                int k0 = bi * 16 + (lane & 3) * 2;
                union { __half2 h; uint32_t u; } p0, p1;
                p0.h = __floats2half2_rn(Wx[(size_t)k0 * G4 + col],
                                         Wx[(size_t)(k0 + 1) * G4 + col]);
                p1.h = __floats2half2_rn(Wx[(size_t)(k0 + 8) * G4 + col],
                                         Wx[(size_t)(k0 + 9) * G4 + col]);
                bx[bi][nb][0] = p0.u;
                bx[bi][nb][1] = p1.u;
            }

        if (tid == 0) g_xzflag[kh] = 0ULL;     // re-zero each launch
        ticket_barrier(&g_bar_all, NCTA);      // start barrier (flags visible)

        for (int t = 0; t < 128; ++t) {
            const int s = 4 * t + 3;
            #pragma unroll 1
            for (int rb = 0; rb < 8; ++rb) {
                // stage x rows [rb*64, +64) (same loader as mains)
                const float* xp =
                    x + ((size_t)(rb * 64 + xrow) * SEQ + s) * DIM + xkb;
                #pragma unroll
                for (int c2 = 0; c2 < 4; ++c2) {
                    float4 v0 = *(const float4*)(xp + c2 * 8);
                    float4 v1 = *(const float4*)(xp + c2 * 8 + 4);
                    union { __half2 h; uint32_t u; } q0, q1, q2, q3;
                    q0.h = __floats2half2_rn(v0.x, v0.y);
                    q1.h = __floats2half2_rn(v0.z, v0.w);
                    q2.h = __floats2half2_rn(v1.x, v1.y);
                    q3.h = __floats2half2_rn(v1.z, v1.w);
                    int k = xkb + c2 * 8;
                    *(uint4*)(sA + a_phys(k >> 4, xrow, (k >> 3) & 1)) =
                        make_uint4(q0.u, q1.u, q2.u, q3.u);
                }
                __syncthreads();

                float acc[2][2][4];
                uint32_t hc[2][2][2];
                #pragma unroll
                for (int mb = 0; mb < 2; ++mb)
                    #pragma unroll
                    for (int nb = 0; nb < 2; ++nb) {
                        #pragma unroll
                        for (int k = 0; k < 4; ++k) acc[mb][nb][k] = 0.f;
                        hc[mb][nb][0] = 0u; hc[mb][nb][1] = 0u;
                    }
                #pragma unroll
                for (int g4 = 0; g4 < 2; ++g4) {
                    #pragma unroll
                    for (int kq = 0; kq < 4; ++kq) {
                        int ks = g4 * 4 + kq;
                        uint32_t am0[4], am1[4];
                        ldsm4(am0, lds0 + ks * 2048);
                        ldsm4(am1, lds1 + ks * 2048);
                        mma_f16acc(hc[0][0], am0, bx[ks][0][0], bx[ks][0][1]);
                        mma_f16acc(hc[0][1], am0, bx[ks][1][0], bx[ks][1][1]);
                        mma_f16acc(hc[1][0], am1, bx[ks][0][0], bx[ks][0][1]);
                        mma_f16acc(hc[1][1], am1, bx[ks][1][0], bx[ks][1][1]);
                    }
                    promote(acc[0][0], hc[0][0]); promote(acc[0][1], hc[0][1]);
                    promote(acc[1][0], hc[1][0]); promote(acc[1][1], hc[1][1]);
                }

                // write xz (fp16) at fragment coordinates
                __half* dst = g_xz + (size_t)t * BATCH * G4;
                #pragma unroll
                for (int mb = 0; mb < 2; ++mb)
                    #pragma unroll
                    for (int nb = 0; nb < 2; ++nb) {
                        union { __half2 h; uint32_t u; } pa, pb;
                        pa.h = __floats2half2_rn(acc[mb][nb][0], acc[mb][nb][1]);
                        pb.h = __floats2half2_rn(acc[mb][nb][2], acc[mb][nb][3]);
                        size_t ra = (size_t)(rb * 64 + Rr[2 * mb]) * G4
                                  + j0h * 4 + cloc[2 * nb];
                        size_t rbw = (size_t)(rb * 64 + Rr[2 * mb + 1]) * G4
                                   + j0h * 4 + cloc[2 * nb];
                        *(uint32_t*)(dst + ra)  = pa.u;
                        *(uint32_t*)(dst + rbw) = pb.u;
                    }
                __syncthreads();
            }
            __threadfence();
            if (tid == 0) atomicAdd(&g_xzflag[kh], 1ULL);
        }
        return;
    }

    // =====================================================================
    //  MAIN CTAs (R8 + xz consumption on s%4==3)
    // =====================================================================
    const int grp = cta >> 4;
    const int r0 = grp * 64;
    const int j0 = (cta & 15) * 16;
    const int jt = cta & 15;
    unsigned long long* const bar_ctr = &g_bar_grp[grp][0];

    uint32_t bfr[NKS][2][2];
    #pragma unroll
    for (int ks = 0; ks < NKS; ++ks)
        #pragma unroll
        for (int nb = 0; nb < 2; ++nb) {
            int n = wN * 16 + nb * 8 + (lane >> 2);
            int col = (n & 3) * HID + j0 + (n >> 2);
            int k0 = ks * 16 + (lane & 3) * 2;
            float w0, w1, w2, w3;
            if (k0 < DIM) {
                w0 = Wx[(size_t)k0 * G4 + col];
                w1 = Wx[(size_t)(k0 + 1) * G4 + col];
                w2 = Wx[(size_t)(k0 + 8) * G4 + col];
                w3 = Wx[(size_t)(k0 + 9) * G4 + col];
            } else {
                w0 = Wh[(size_t)(k0 - DIM) * G4 + col];
                w1 = Wh[(size_t)(k0 - DIM + 1) * G4 + col];
                w2 = Wh[(size_t)(k0 - DIM + 8) * G4 + col];
                w3 = Wh[(size_t)(k0 - DIM + 9) * G4 + col];
            }
            union { __half2 h; uint32_t u; } p0, p1;
            p0.h = __floats2half2_rn(w0, w1);
            p1.h = __floats2half2_rn(w2, w3);
            bfr[ks][nb][0] = p0.u;
            bfr[ks][nb][1] = p1.u;
        }

    ((uint2*)g_h16[0])[cta * NTHR + tid] = make_uint2(0u, 0u);

    const int myOdd = lane & 1;
    const int rA = wM * 32 + myOdd * 16 + (lane >> 2);
    float bI[2], bF[2], bG[2], bO[2];
    #pragma unroll
    for (int nb = 0; nb < 2; ++nb) {
        int j = j0 + wN * 4 + nb * 2 + (q >> 1);
        bI[nb] = bv[j];
        bF[nb] = bv[HID + j];
        bG[nb] = bv[2 * HID + j];
        bO[nb] = bv[3 * HID + j];
    }
    float cst[4] = {0.f, 0.f, 0.f, 0.f};

    // prologue: stage x(0)
    {
        const float* xp = x + ((size_t)(r0 + xrow) * SEQ + 0) * DIM + xkb;
        #pragma unroll
        for (int c2 = 0; c2 < 4; ++c2) {
            float4 v0 = *(const float4*)(xp + c2 * 8);
            float4 v1 = *(const float4*)(xp + c2 * 8 + 4);
            union { __half2 h; uint32_t u; } q0, q1, q2, q3;
            q0.h = __floats2half2_rn(v0.x, v0.y);
            q1.h = __floats2half2_rn(v0.z, v0.w);
            q2.h = __floats2half2_rn(v1.x, v1.y);
            q3.h = __floats2half2_rn(v1.z, v1.w);
            int k = xkb + c2 * 8;
            *(uint4*)(sA + a_phys(k >> 4, xrow, (k >> 3) & 1)) =
                make_uint4(q0.u, q1.u, q2.u, q3.u);
        }
    }

    ticket_barrier(&g_bar_all, NCTA);    // global start (h0, flags, x(0))

    for (int s = 0; s < SEQ; ++s) {
        const bool skipx = ((s & 3) == 3);

        const __half* hp = g_h16[s & 1];
        const uint4* hsrc = (const uint4*)(hp + (size_t)(r0 + xrow) * HID + hkb);
        uint4 hr[8];
        #pragma unroll
        for (int c = 0; c < 8; ++c) hr[c] = __ldcv(hsrc + c);

        float acc[2][2][4];
        uint32_t hc[2][2][2];
        #pragma unroll
        for (int mb = 0; mb < 2; ++mb)
            #pragma unroll
            for (int nb = 0; nb < 2; ++nb) {
                #pragma unroll
                for (int k = 0; k < 4; ++k) acc[mb][nb][k] = 0.f;
                hc[mb][nb][0] = 0u; hc[mb][nb][1] = 0u;
            }

        if (!skipx) {
            #pragma unroll
            for (int g4 = 0; g4 < 2; ++g4) {
                #pragma unroll
                for (int kq = 0; kq < 4; ++kq) {
                    int ks = g4 * 4 + kq;
                    uint32_t am0[4], am1[4];
                    ldsm4(am0, lds0 + ks * 2048);
                    ldsm4(am1, lds1 + ks * 2048);
                    mma_f16acc(hc[0][0], am0, bfr[ks][0][0], bfr[ks][0][1]);
                    mma_f16acc(hc[0][1], am0, bfr[ks][1][0], bfr[ks][1][1]);
                    mma_f16acc(hc[1][0], am1, bfr[ks][0][0], bfr[ks][0][1]);
                    mma_f16acc(hc[1][1], am1, bfr[ks][1][0], bfr[ks][1][1]);
                }
                promote(acc[0][0], hc[0][0]); promote(acc[0][1], hc[0][1]);
                promote(acc[1][0], hc[1][0]); promote(acc[1][1], hc[1][1]);
            }
        }

        #pragma unroll
        for (int c = 0; c < 8; ++c) {
            int kg = DIM + hkb + c * 8;
            *(uint4*)(sA + a_phys(kg >> 4, xrow, (kg >> 3) & 1)) = hr[c];
        }
        __syncthreads();

        #pragma unroll
        for (int g4 = 0; g4 < 4; ++g4) {
            #pragma unroll
            for (int kq = 0; kq < 4; ++kq) {
                int ks = 8 + g4 * 4 + kq;
                uint32_t am0[4], am1[4];
                ldsm4(am0, lds0 + ks * 2048);
                ldsm4(am1, lds1 + ks * 2048);
                mma_f16acc(hc[0][0], am0, bfr[ks][0][0], bfr[ks][0][1]);
                mma_f16acc(hc[0][1], am0, bfr[ks][1][0], bfr[ks][1][1]);
                mma_f16acc(hc[1][0], am1, bfr[ks][0][0], bfr[ks][0][1]);
                mma_f16acc(hc[1][1], am1, bfr[ks][1][0], bfr[ks][1][1]);
            }
            promote(acc[0][0], hc[0][0]); promote(acc[0][1], hc[0][1]);
            promote(acc[1][0], hc[1][0]); promote(acc[1][1], hc[1][1]);
        }

        if (skipx) {
            const int t = s >> 2;
            if (tid == 0) {
                unsigned long long v;
                do {
                    asm volatile("ld.acquire.gpu.u64 %0, [%1];"
                                 : "=l"(v) : "l"(&g_xzflag[jt]) : "memory");
                } while (v < (unsigned long long)(t + 1));
            }
            __syncthreads();
            const __half* src = g_xz + (size_t)t * BATCH * G4;
            #pragma unroll
            for (int mb = 0; mb < 2; ++mb)
                #pragma unroll
                for (int nb = 0; nb < 2; ++nb) {
                    uint32_t ua = *(const uint32_t*)(src +
                        (size_t)(r0 + Rr[2 * mb]) * G4 + j0 * 4 + cloc[2 * nb]);
                    uint32_t ub = *(const uint32_t*)(src +
                        (size_t)(r0 + Rr[2 * mb + 1]) * G4 + j0 * 4 + cloc[2 * nb]);
                    union { uint32_t u; __half2 h; } ca, cb;
                    ca.u = ua; cb.u = ub;
                    float2 fa = __half22float2(ca.h);
                    float2 fb = __half22float2(cb.h);
                    acc[mb][nb][0] += fa.x; acc[mb][nb][1] += fa.y;
                    acc[mb][nb][2] += fb.x; acc[mb][nb][3] += fb.y;
                }
        }

        // gate exchange + cell update (R8)
        float zif[2][4], zgo[2][4];
        #pragma unroll
        for (int nb = 0; nb < 2; ++nb)
            #pragma unroll
            for (int k = 0; k < 4; ++k) {
                float s0 = __shfl_xor_sync(0xffffffffu, acc[0][nb][k], 1);
                float s1 = __shfl_xor_sync(0xffffffffu, acc[1][nb][k], 1);
                zif[nb][k] = myOdd ? s1 : acc[0][nb][k];
                zgo[nb][k] = myOdd ? acc[1][nb][k] : s0;
            }

        __half* hn = g_h16[(s + 1) & 1];
        #pragma unroll
        for (int nb = 0; nb < 2; ++nb) {
            int j = j0 + wN * 4 + nb * 2 + (q >> 1);
            float i0 = sig_mufu(zif[nb][0] + bI[nb]);
            float f0 = sig_mufu(zif[nb][1] + bF[nb]);
            float g0 = tanh_mufu(zgo[nb][0] + bG[nb]);
            float o0 = sig_mufu(zgo[nb][1] + bO[nb]);
            float i1 = sig_mufu(zif[nb][2] + bI[nb]);
            float f1 = sig_mufu(zif[nb][3] + bF[nb]);
            float g1 = tanh_mufu(zgo[nb][2] + bG[nb]);
            float o1 = sig_mufu(zgo[nb][3] + bO[nb]);
            cst[nb * 2 + 0] = f0 * cst[nb * 2 + 0] + i0 * g0;
            cst[nb * 2 + 1] = f1 * cst[nb * 2 + 1] + i1 * g1;
            hn[(size_t)(r0 + rA) * HID + j] =
                __float2half_rn(o0 * tanh_mufu(cst[nb * 2 + 0]));
            hn[(size_t)(r0 + rA + 8) * HID + j] =
                __float2half_rn(o1 * tanh_mufu(cst[nb * 2 + 1]));
        }

        // split barrier: arrive, stage x(s+1) if next step needs it, wait
        __syncthreads();
        unsigned long long tick = 0;
        if (tid == 0) {
            asm volatile("atom.add.release.gpu.global.u64 %0, [%1], 1;"
                         : "=l"(tick) : "l"(bar_ctr) : "memory");
            tick += 1ULL;
        }
        if (s + 1 < SEQ && ((s + 1) & 3) != 3) {
            const float* xp = x + ((size_t)(r0 + xrow) * SEQ + (s + 1)) * DIM + xkb;
            #pragma unroll
            for (int c2 = 0; c2 < 4; ++c2) {
                float4 v0 = *(const float4*)(xp + c2 * 8);
                float4 v1 = *(const float4*)(xp + c2 * 8 + 4);
                union { __half2 h; uint32_t u; } q0, q1, q2, q3;
                q0.h = __floats2half2_rn(v0.x, v0.y);
                q1.h = __floats2half2_rn(v0.z, v0.w);
                q2.h = __floats2half2_rn(v1.x, v1.y);
                q3.h = __floats2half2_rn(v1.z, v1.w);
                int k = xkb + c2 * 8;
                *(uint4*)(sA + a_phys(k >> 4, xrow, (k >> 3) & 1)) =
                    make_uint4(q0.u, q1.u, q2.u, q3.u);
            }
        }
        if (tid == 0) {
            unsigned long long target =
                ((tick + (unsigned long long)NGRP - 1ULL) / NGRP) *
                (unsigned long long)NGRP;
            unsigned long long v;
            do {
                asm volatile("ld.acquire.gpu.u64 %0, [%1];"
                             : "=l"(v) : "l"(bar_ctr) : "memory");
            } while (v < target);
        }
        __syncthreads();
    }

    // classifier + softmax (R8)
    if (warp < 4) {
        const int row = cta * 4 + warp;
        const __half* hf = g_h16[0];
        float acc10[10];
        #pragma unroll
        for (int c = 0; c < 10; ++c) acc10[c] = 0.f;
        uint4 hv = __ldcv((const uint4*)(hf + (size_t)row * HID + lane * 8));
        const __half* hvh = (const __half*)&hv;
        #pragma unroll
        for (int u = 0; u < 8; ++u) {
            float h = __half2float(hvh[u]);
            const float* wd = Wd + (size_t)(lane * 8 + u) * 10;
            #pragma unroll
            for (int c = 0; c < 10; ++c) acc10[c] += h * wd[c];
        }
        #pragma unroll
        for (int off = 16; off > 0; off >>= 1) {
            #pragma unroll
            for (int c = 0; c < 10; ++c)
                acc10[c] += __shfl_down_sync(0xffffffffu, acc10[c], off);
        }
        if (lane == 0) {
            float m = -3.0e38f;
            #pragma unroll
            for (int c = 0; c < 10; ++c) { acc10[c] += bd[c]; m = fmaxf(m, acc10[c]); }
            float ssum = 0.f;
            #pragma unroll
            for (int c = 0; c < 10; ++c) { acc10[c] = __expf(acc10[c] - m); ssum += acc10[c]; }
            float inv = 1.0f / ssum;
            #pragma unroll
            for (int c = 0; c < 10; ++c) out[(size_t)row * 10 + c] = acc10[c] * inv;
        }
    }
}

extern "C" void kernel_launch(void* const* d_in, const int* in_sizes, int n_in,
                              void* d_out, int out_size) {
    const float* x  = (const float*)d_in[0];
    const float* Wx = (const float*)d_in[1];
    const float* Wh = (const float*)d_in[2];
    const float* b  = (const float*)d_in[3];
    const float* Wd = (const float*)d_in[4];
    const float* bd = (const float*)d_in[5];
    (void)in_sizes; (void)n_in; (void)out_size;
    lstm_prod<<<NCTA, NTHR>>>(x, Wx, Wh, b, Wd, bd, (float*)d_out);
}

// round 17
// speedup vs baseline: 1.2363x; 1.2363x over previous
#include <cuda_runtime.h>
#include <cuda_fp16.h>
#include <cstdint>
#include <cstddef>

// R16: R8 split into 2 CTAs per SM for cross-CTA port-gap filling.
// Port model (R8-R15): SMSP issue port is serial; emulated HMMA ~55 port-cyc;
// R8 = optimal mix at ~94% of its floor; remaining ~0.7k cyc/step of
// h-roundtrip/loader/barrier exposure idles the port because 1 CTA/SM.
// Now: 256 CTAs x 128 thr, tile 32 rows x 64 cols, 16 bands x 16 j-tiles;
// co-resident CTAs belong to different barrier groups -> desynchronized
// stalls, one CTA's MMAs fill the other's port gaps. Math identical to R8.

#define SEQ   512
#define BATCH 512
#define DIM   128
#define HID   256
#define G4    1024
#define NCTA  256
#define NTHR  128
#define NKS   24
#define NGRP  16             // CTAs per barrier group (one 32-row band)

// ---- persistent device scratch ----
__device__ __align__(16) __half g_h16[2][BATCH * HID];
__device__ __align__(128) unsigned long long g_bar_grp[16][16];  // 128B apart

__device__ __forceinline__ uint32_t smem_u32(const void* p) {
    uint32_t a;
    asm("{ .reg .u64 t; cvta.to.shared.u64 t, %1; cvt.u32.u64 %0, t; }"
        : "=r"(a) : "l"(p));
    return a;
}
__device__ __forceinline__ void ldsm4(uint32_t a[4], uint32_t addr) {
    asm volatile("ldmatrix.sync.aligned.m8n8.x4.shared.b16 {%0,%1,%2,%3}, [%4];"
                 : "=r"(a[0]), "=r"(a[1]), "=r"(a[2]), "=r"(a[3]) : "r"(addr));
}
__device__ __forceinline__ void mma_f16acc(uint32_t c[2], const uint32_t a[4],
                                           uint32_t b0, uint32_t b1) {
    asm volatile(
        "mma.sync.aligned.m16n8k16.row.col.f16.f16.f16.f16 "
        "{%0,%1}, {%2,%3,%4,%5}, {%6,%7}, {%0,%1};"
        : "+r"(c[0]), "+r"(c[1])
        : "r"(a[0]), "r"(a[1]), "r"(a[2]), "r"(a[3]), "r"(b0), "r"(b1));
}
__device__ __forceinline__ void promote(float acc[4], uint32_t hc[2]) {
    float2 lo = __half22float2(*reinterpret_cast<__half2*>(&hc[0]));
    float2 hi = __half22float2(*reinterpret_cast<__half2*>(&hc[1]));
    acc[0] += lo.x; acc[1] += lo.y; acc[2] += hi.x; acc[3] += hi.y;
    hc[0] = 0u; hc[1] = 0u;
}
__device__ __forceinline__ float tanh_mufu(float x) {
    float y;
    asm("tanh.approx.f32 %0, %1;" : "=f"(y) : "f"(x));
    return y;
}
__device__ __forceinline__ float sig_mufu(float x) {
    return fmaf(0.5f, tanh_mufu(0.5f * x), 0.5f);
}
// A tile: 24 ks blocks of 32 rows x 32B (1024B each), XOR swizzle for ldsm.
__device__ __forceinline__ uint32_t a_phys(int ks, int row, int kh) {
    return (uint32_t)(ks * 1024 + row * 32 + ((kh << 4) ^ ((row & 4) << 2)));
}

__global__ void __launch_bounds__(NTHR, 2)
lstm_hmma2(const float* __restrict__ x,  const float* __restrict__ Wx,
           const float* __restrict__ Wh, const float* __restrict__ bv,
           const float* __restrict__ Wd, const float* __restrict__ bd,
           float* __restrict__ out)
{
    __shared__ __align__(1024) char sA[NKS * 1024];   // 24 KB: [x_t | h] fp16
    const uint32_t sA_u = smem_u32(sA);

    const int tid  = threadIdx.x;
    const int cta  = blockIdx.x;
    const int warp = tid >> 5, lane = tid & 31;
    const int band = cta >> 4;          // 0..15 (32-row band)
    const int r0 = band * 32;
    const int j0 = (cta & 15) * 16;     // 16 hidden cols
    const int wN = warp;                // 4-way N split (16 n-cols each)
    unsigned long long* const bar_ctr = &g_bar_grp[band][0];

    // ---- one-time: B fragments into registers (identical layout to R8) ----
    uint32_t bfr[NKS][2][2];
    #pragma unroll
    for (int ks = 0; ks < NKS; ++ks)
        #pragma unroll
        for (int nb = 0; nb < 2; ++nb) {
            int n = wN * 16 + nb * 8 + (lane >> 2);
            int col = (n & 3) * HID + j0 + (n >> 2);
            int k0 = ks * 16 + (lane & 3) * 2;
            float w0, w1, w2, w3;
            if (k0 < DIM) {
                w0 = Wx[(size_t)k0 * G4 + col];
                w1 = Wx[(size_t)(k0 + 1) * G4 + col];
                w2 = Wx[(size_t)(k0 + 8) * G4 + col];
                w3 = Wx[(size_t)(k0 + 9) * G4 + col];
            } else {
                w0 = Wh[(size_t)(k0 - DIM) * G4 + col];
                w1 = Wh[(size_t)(k0 - DIM + 1) * G4 + col];
                w2 = Wh[(size_t)(k0 - DIM + 8) * G4 + col];
                w3 = Wh[(size_t)(k0 - DIM + 9) * G4 + col];
            }
            union { __half2 h; uint32_t u; } p0, p1;
            p0.h = __floats2half2_rn(w0, w1);
            p1.h = __floats2half2_rn(w2, w3);
            bfr[ks][nb][0] = p0.u;
            bfr[ks][nb][1] = p1.u;
        }

    // zero h buffer 0 (32768 threads x 8B = 256KB)
    ((uint2*)g_h16[0])[cta * NTHR + tid] = make_uint2(0u, 0u);

    // epilogue geometry (R8 with wM removed; band is 32 rows = 2 m16 tiles)
    const int q = lane & 3;
    const int myOdd = lane & 1;
    const int rA = myOdd * 16 + (lane >> 2);      // rows rA, rA+8 in band
    float bI[2], bF[2], bG[2], bO[2];
    #pragma unroll
    for (int nb = 0; nb < 2; ++nb) {
        int j = j0 + wN * 4 + nb * 2 + (q >> 1);
        bI[nb] = bv[j];
        bF[nb] = bv[HID + j];
        bG[nb] = bv[2 * HID + j];
        bO[nb] = bv[3 * HID + j];
    }
    float cst[4] = {0.f, 0.f, 0.f, 0.f};

    // loader coords: 128 threads stage 32 rows
    const int xrow = tid >> 2, xkb = (tid & 3) * 32;  // x: 32 floats/thread
    const int hkb  = (tid & 3) * 64;                  // h: 64 halfs/thread

    // ldmatrix addr bases (two m16 tiles of the 32-row band)
    const int lrow = lane & 15, lkh = lane >> 4;
    uint32_t lds0 = sA_u + a_phys(0, lrow, lkh);
    uint32_t lds1 = sA_u + a_phys(0, 16 + lrow, lkh);

    // ---- prologue: stage x(0) ----
    {
        const float* xp = x + ((size_t)(r0 + xrow) * SEQ + 0) * DIM + xkb;
        #pragma unroll
        for (int c2 = 0; c2 < 4; ++c2) {
            float4 v0 = *(const float4*)(xp + c2 * 8);
            float4 v1 = *(const float4*)(xp + c2 * 8 + 4);
            union { __half2 h; uint32_t u; } q0, q1, q2, q3;
            q0.h = __floats2half2_rn(v0.x, v0.y);
            q1.h = __floats2half2_rn(v0.z, v0.w);
            q2.h = __floats2half2_rn(v1.x, v1.y);
            q3.h = __floats2half2_rn(v1.z, v1.w);
            int k = xkb + c2 * 8;
            *(uint4*)(sA + a_phys(k >> 4, xrow, (k >> 3) & 1)) =
                make_uint4(q0.u, q1.u, q2.u, q3.u);
        }
    }

    // full group barrier once (h0 zero + x(0) visible within band)
    {
        __syncthreads();
        if (tid == 0) {
            __threadfence();
            unsigned long long t = atomicAdd(bar_ctr, 1ULL) + 1ULL;
            unsigned long long target =
                ((t + (unsigned long long)NGRP - 1ULL) / NGRP) *
                (unsigned long long)NGRP;
            unsigned long long v;
            do {
                asm volatile("ld.acquire.gpu.u64 %0, [%1];"
                             : "=l"(v) : "l"(bar_ctr) : "memory");
            } while (v < target);
        }
        __syncthreads();
    }

    for (int s = 0; s < SEQ; ++s) {
        // h loads first (L1-bypass); latency hides under x-part MMAs
        const __half* hp = g_h16[s & 1];
        const uint4* hsrc = (const uint4*)(hp + (size_t)(r0 + xrow) * HID + hkb);
        uint4 hr[8];
        #pragma unroll
        for (int c = 0; c < 8; ++c) hr[c] = __ldcv(hsrc + c);

        float acc[2][2][4];      // [m16 tile][nb][frag]
        uint32_t hc[2][2][2];
        #pragma unroll
        for (int mb = 0; mb < 2; ++mb)
            #pragma unroll
            for (int nb = 0; nb < 2; ++nb) {
                #pragma unroll
                for (int k = 0; k < 4; ++k) acc[mb][nb][k] = 0.f;
                hc[mb][nb][0] = 0u; hc[mb][nb][1] = 0u;
            }

        // x-part MMAs (ks 0..7), promote every 4
        #pragma unroll
        for (int g4 = 0; g4 < 2; ++g4) {
            #pragma unroll
            for (int kq = 0; kq < 4; ++kq) {
                int ks = g4 * 4 + kq;
                uint32_t am0[4], am1[4];
                ldsm4(am0, lds0 + ks * 1024);
                ldsm4(am1, lds1 + ks * 1024);
                mma_f16acc(hc[0][0], am0, bfr[ks][0][0], bfr[ks][0][1]);
                mma_f16acc(hc[0][1], am0, bfr[ks][1][0], bfr[ks][1][1]);
                mma_f16acc(hc[1][0], am1, bfr[ks][0][0], bfr[ks][0][1]);
                mma_f16acc(hc[1][1], am1, bfr[ks][1][0], bfr[ks][1][1]);
            }
            promote(acc[0][0], hc[0][0]); promote(acc[0][1], hc[0][1]);
            promote(acc[1][0], hc[1][0]); promote(acc[1][1], hc[1][1]);
        }

        // stage h (full 64 halfs per thread)
        #pragma unroll
        for (int c = 0; c < 8; ++c) {
            int kg = DIM + hkb + c * 8;
            *(uint4*)(sA + a_phys(kg >> 4, xrow, (kg >> 3) & 1)) = hr[c];
        }
        __syncthreads();

        // h-part MMAs (ks 8..23), promote every 4
        #pragma unroll
        for (int g4 = 0; g4 < 4; ++g4) {
            #pragma unroll
            for (int kq = 0; kq < 4; ++kq) {
                int ks = 8 + g4 * 4 + kq;
                uint32_t am0[4], am1[4];
                ldsm4(am0, lds0 + ks * 1024);
                ldsm4(am1, lds1 + ks * 1024);
                mma_f16acc(hc[0][0], am0, bfr[ks][0][0], bfr[ks][0][1]);
                mma_f16acc(hc[0][1], am0, bfr[ks][1][0], bfr[ks][1][1]);
                mma_f16acc(hc[1][0], am1, bfr[ks][0][0], bfr[ks][0][1]);
                mma_f16acc(hc[1][1], am1, bfr[ks][1][0], bfr[ks][1][1]);
            }
            promote(acc[0][0], hc[0][0]); promote(acc[0][1], hc[0][1]);
            promote(acc[1][0], hc[1][0]); promote(acc[1][1], hc[1][1]);
        }

        // gate exchange (R8): even lanes own (i,f), odd own (g,o)
        float zif[2][4], zgo[2][4];
        #pragma unroll
        for (int nb = 0; nb < 2; ++nb)
            #pragma unroll
            for (int k = 0; k < 4; ++k) {
                float s0 = __shfl_xor_sync(0xffffffffu, acc[0][nb][k], 1);
                float s1 = __shfl_xor_sync(0xffffffffu, acc[1][nb][k], 1);
                zif[nb][k] = myOdd ? s1 : acc[0][nb][k];
                zgo[nb][k] = myOdd ? acc[1][nb][k] : s0;
            }

        __half* hn = g_h16[(s + 1) & 1];
        #pragma unroll
        for (int nb = 0; nb < 2; ++nb) {
            int j = j0 + wN * 4 + nb * 2 + (q >> 1);
            float i0 = sig_mufu(zif[nb][0] + bI[nb]);
            float f0 = sig_mufu(zif[nb][1] + bF[nb]);
            float g0 = tanh_mufu(zgo[nb][0] + bG[nb]);
            float o0 = sig_mufu(zgo[nb][1] + bO[nb]);
            float i1 = sig_mufu(zif[nb][2] + bI[nb]);
            float f1 = sig_mufu(zif[nb][3] + bF[nb]);
            float g1 = tanh_mufu(zgo[nb][2] + bG[nb]);
            float o1 = sig_mufu(zgo[nb][3] + bO[nb]);
            cst[nb * 2 + 0] = f0 * cst[nb * 2 + 0] + i0 * g0;
            cst[nb * 2 + 1] = f1 * cst[nb * 2 + 1] + i1 * g1;
            hn[(size_t)(r0 + rA) * HID + j] =
                __float2half_rn(o0 * tanh_mufu(cst[nb * 2 + 0]));
            hn[(size_t)(r0 + rA + 8) * HID + j] =
                __float2half_rn(o1 * tanh_mufu(cst[nb * 2 + 1]));
        }

        // split barrier: arrive, stage x(s+1) in the window, wait
        __syncthreads();
        unsigned long long tick = 0;
        if (tid == 0) {
            asm volatile("atom.add.release.gpu.global.u64 %0, [%1], 1;"
                         : "=l"(tick) : "l"(bar_ctr) : "memory");
            tick += 1ULL;
        }
        if (s + 1 < SEQ) {
            const float* xp = x + ((size_t)(r0 + xrow) * SEQ + (s + 1)) * DIM + xkb;
            #pragma unroll
            for (int c2 = 0; c2 < 4; ++c2) {
                float4 v0 = *(const float4*)(xp + c2 * 8);
                float4 v1 = *(const float4*)(xp + c2 * 8 + 4);
                union { __half2 h; uint32_t u; } q0, q1, q2, q3;
                q0.h = __floats2half2_rn(v0.x, v0.y);
                q1.h = __floats2half2_rn(v0.z, v0.w);
                q2.h = __floats2half2_rn(v1.x, v1.y);
                q3.h = __floats2half2_rn(v1.z, v1.w);
                int k = xkb + c2 * 8;
                *(uint4*)(sA + a_phys(k >> 4, xrow, (k >> 3) & 1)) =
                    make_uint4(q0.u, q1.u, q2.u, q3.u);
            }
        }
        if (tid == 0) {
            unsigned long long target =
                ((tick + (unsigned long long)NGRP - 1ULL) / NGRP) *
                (unsigned long long)NGRP;
            unsigned long long v;
            do {
                asm volatile("ld.acquire.gpu.u64 %0, [%1];"
                             : "=l"(v) : "l"(bar_ctr) : "memory");
            } while (v < target);
        }
        __syncthreads();
    }

    // ---- classifier + softmax: 256 CTAs x 2 warps = 512 rows (band-local) --
    if (warp < 2) {
        const int row = cta * 2 + warp;
        const __half* hf = g_h16[0];
        float acc10[10];
        #pragma unroll
        for (int c = 0; c < 10; ++c) acc10[c] = 0.f;
        uint4 hv = __ldcv((const uint4*)(hf + (size_t)row * HID + lane * 8));
        const __half* hvh = (const __half*)&hv;
        #pragma unroll
        for (int u = 0; u < 8; ++u) {
            float h = __half2float(hvh[u]);
            const float* wd = Wd + (size_t)(lane * 8 + u) * 10;
            #pragma unroll
            for (int c = 0; c < 10; ++c) acc10[c] += h * wd[c];
        }
        #pragma unroll
        for (int off = 16; off > 0; off >>= 1) {
            #pragma unroll
            for (int c = 0; c < 10; ++c)
                acc10[c] += __shfl_down_sync(0xffffffffu, acc10[c], off);
        }
        if (lane == 0) {
            float m = -3.0e38f;
            #pragma unroll
            for (int c = 0; c < 10; ++c) { acc10[c] += bd[c]; m = fmaxf(m, acc10[c]); }
            float ssum = 0.f;
            #pragma unroll
            for (int c = 0; c < 10; ++c) { acc10[c] = __expf(acc10[c] - m); ssum += acc10[c]; }
            float inv = 1.0f / ssum;
            #pragma unroll
            for (int c = 0; c < 10; ++c) out[(size_t)row * 10 + c] = acc10[c] * inv;
        }
    }
}

extern "C" void kernel_launch(void* const* d_in, const int* in_sizes, int n_in,
                              void* d_out, int out_size) {
    const float* x  = (const float*)d_in[0];
    const float* Wx = (const float*)d_in[1];
    const float* Wh = (const float*)d_in[2];
    const float* b  = (const float*)d_in[3];
    const float* Wd = (const float*)d_in[4];
    const float* bd = (const float*)d_in[5];
    (void)in_sizes; (void)n_in; (void)out_size;
    lstm_hmma2<<<NCTA, NTHR>>>(x, Wx, Wh, b, Wd, bd, (float*)d_out);
}